// round 16
// baseline (speedup 1.0000x reference)
#include <cuda_runtime.h>
#include <cuda_bf16.h>

#define TRUNC 2048
#define TLEN  2048
#define CAPV  200
#define RPB   2     // rows per block

// ---------------------------------------------------------------------------
// Champion kernel (locked in after 14 rounds of structural search).
// Fused single kernel. One block = (2 rows, 1 channel), grid (1024, 8).
// The store path runs at its effective chip cap (~6.2 TB/s into L1/LTS);
// the timed total sits on a ~24.5 us environment floor that no structural
// variant pierced (8 variants tested: RPB 1/2/4, 128-512 threads,
// persistent one-wave, PDL two-phase, .cs vs writeback, v8 stores).
//
// Per block: build this channel's 201-entry f(L) table in SMEM using
// MUFU-only math (fully hidden behind the store stream), then fill:
//   j > i                 -> 0                      (upper triangle)
//   d = i-j > far_thresh  -> constant pattern       (no table)
//   else                  -> table lookups          (narrow diagonal band)
// Channels:
//   ch0,1 : ipow(tanh(eta[h]), L)
//   ch2   : dilate(ipow(tanh(eta[2]), .), n=4)
//   ch3,4 : sigmoid(nu[h])^L * cos(theta[h]*L)
//   ch5   : sigmoid(nu[2])^L * sin(theta[2]*L)
//   ch6   : dilate(cos(theta[3]*.), n=3) * cos(theta[3]*L)
//   ch7   : dilate(sin(theta[4]*.), n=2) * sin(theta[4]*L)
// then tril(.) - eye.
// ---------------------------------------------------------------------------
__global__ __launch_bounds__(256)
void rem_kernel(const float* __restrict__ eta,
                const float* __restrict__ nu,
                const float* __restrict__ theta,
                float* __restrict__ out)
{
    __shared__ float tab[224];

    const int ch = blockIdx.y;
    const int i0 = blockIdx.x * RPB;
    const int t  = threadIdx.x;
    const float4 zero4 = make_float4(0.f, 0.f, 0.f, 0.f);

    // ---- build table (201 entries), MUFU-only math ----
    if (t <= CAPV) {
        float fl = (float)t;
        float v;
        if (ch < 3) {
            // tanh(x) = 1 - 2/(e^{2x}+1)  (MUFU exp + rcp)
            float x   = eta[ch];
            float lam = 1.0f - 2.0f * __frcp_rn(__expf(2.0f * x) + 1.0f);
            if (t == 0) {
                v = 1.0f;
            } else {
                v = exp2f(fl * __log2f(fabsf(lam)));
                if ((t & 1) && lam < 0.0f) v = -v;
            }
        } else if (ch < 6) {
            int h = ch - 3;
            float x  = nu[h];
            // sigmoid(x)^L = exp2(-L * log2(1 + e^-x))
            float lg  = -__log2f(1.0f + __expf(-x));
            float mag = exp2f(fl * lg);
            float ang = theta[h] * fl;
            v = mag * ((h == 2) ? __sinf(ang) : __cosf(ang));
        } else {
            int h = ch - 3;          // 3, 4
            float ang = theta[h] * fl;
            v = (h == 3) ? __cosf(ang) : __sinf(ang);
        }
        tab[t] = v;
    }
    __syncthreads();

    int farth;                    // groups with jb < i - farth are "far"
    if      (ch == 2) farth = 806;
    else if (ch == 6) farth = 608;
    else              farth = 203;

    #pragma unroll
    for (int r = 0; r < RPB; r++) {
        const int i = i0 + r;
        float4* __restrict__ row4 =
            (float4*)(out + ((size_t)ch * TRUNC + (size_t)i) * TLEN);

        // far-region pattern for this (ch, i): j-independent except ch6
        float4 farv;
        if (ch == 2) {
            int im = i & 3;
            farv.x = (im == 0) ? 1.f : 0.f;
            farv.y = (im == 1) ? 1.f : 0.f;
            farv.z = (im == 2) ? 1.f : 0.f;
            farv.w = (im == 3) ? 1.f : 0.f;
        } else if (ch == 5 || ch == 7) {
            farv = zero4;
        } else {
            farv = make_float4(1.f, 1.f, 1.f, 1.f);
        }

        #pragma unroll
        for (int g = 0; g < 2; g++) {
            int q  = t + (g << 8);
            int jb = q << 2;
            float4 rr;
            if (jb > i) {
                rr = zero4;
            } else if (jb < i - farth) {
                if (ch == 6) {
                    unsigned r3 = (unsigned)(i - jb) % 3u;
                    rr.x = (r3 == 0u) ? 1.f : 0.f;
                    rr.y = (r3 == 1u) ? 1.f : 0.f;
                    rr.z = (r3 == 2u) ? 1.f : 0.f;
                    rr.w = (r3 == 0u) ? 1.f : 0.f;
                } else {
                    rr = farv;
                }
            } else {
                // diagonal band: table lookups (general path, covers all d >= 0)
                #pragma unroll
                for (int k = 0; k < 4; k++) {
                    int d = i - jb - k;
                    float v = 0.0f;
                    if (d >= 0) {
                        if (ch == 2) {
                            if ((d & 3) == 0) {
                                int dq = d >> 2;
                                v = tab[(dq > CAPV) ? 0 : dq];
                            }
                        } else if (ch == 6) {
                            unsigned ud = (unsigned)d;
                            if (ud % 3u == 0u) {
                                unsigned dq = ud / 3u;
                                v = tab[(dq > CAPV) ? 0 : (int)dq]
                                  * tab[(d  > CAPV) ? 0 : d];
                            }
                        } else if (ch == 7) {
                            if (d <= CAPV && (d & 1) == 0)
                                v = tab[d >> 1] * tab[d];
                        } else {
                            v = tab[(d > CAPV) ? 0 : d];
                        }
                        if (d == 0) v -= 1.0f;
                    }
                    ((float*)&rr)[k] = v;
                }
            }
            row4[q] = rr;
        }
    }
}

extern "C" void kernel_launch(void* const* d_in, const int* in_sizes, int n_in,
                              void* d_out, int out_size)
{
    const float* eta   = (const float*)d_in[0];
    const float* nu    = (const float*)d_in[1];
    const float* theta = (const float*)d_in[2];
    float* out = (float*)d_out;

    rem_kernel<<<dim3(TRUNC / RPB, 8), 256>>>(eta, nu, theta, out);
}

// round 17
// speedup vs baseline: 1.0013x; 1.0013x over previous
#include <cuda_runtime.h>
#include <cuda_bf16.h>

#define TRUNC 2048
#define TLEN  2048
#define CAPV  200
#define RPB   2     // rows per block

// ---------------------------------------------------------------------------
// FINAL champion kernel (converged; 24.576 us reproduced x3: R11/R14/R16).
// Fused single kernel. One block = (2 rows, 1 channel), grid (1024, 8).
// Store stream runs at the effective chip store-path cap (~6.2 TB/s,
// consistent with the HW-measured ~6300 B/cyc LTS ceiling, path-independent);
// remaining total-vs-kernel gap is graph-replay overhead.
//
// Per block: build this channel's 201-entry f(L) table in SMEM using
// MUFU-only math (fully hidden behind the store stream), then fill:
//   j > i                 -> 0                      (upper triangle)
//   d = i-j > far_thresh  -> constant pattern       (no table)
//   else                  -> table lookups          (narrow diagonal band)
// Channels:
//   ch0,1 : ipow(tanh(eta[h]), L)
//   ch2   : dilate(ipow(tanh(eta[2]), .), n=4)
//   ch3,4 : sigmoid(nu[h])^L * cos(theta[h]*L)
//   ch5   : sigmoid(nu[2])^L * sin(theta[2]*L)
//   ch6   : dilate(cos(theta[3]*.), n=3) * cos(theta[3]*L)
//   ch7   : dilate(sin(theta[4]*.), n=2) * sin(theta[4]*L)
// then tril(.) - eye.
// ---------------------------------------------------------------------------
__global__ __launch_bounds__(256)
void rem_kernel(const float* __restrict__ eta,
                const float* __restrict__ nu,
                const float* __restrict__ theta,
                float* __restrict__ out)
{
    __shared__ float tab[224];

    const int ch = blockIdx.y;
    const int i0 = blockIdx.x * RPB;
    const int t  = threadIdx.x;
    const float4 zero4 = make_float4(0.f, 0.f, 0.f, 0.f);

    // ---- build table (201 entries), MUFU-only math ----
    if (t <= CAPV) {
        float fl = (float)t;
        float v;
        if (ch < 3) {
            // tanh(x) = 1 - 2/(e^{2x}+1)  (MUFU exp + rcp)
            float x   = eta[ch];
            float lam = 1.0f - 2.0f * __frcp_rn(__expf(2.0f * x) + 1.0f);
            if (t == 0) {
                v = 1.0f;
            } else {
                v = exp2f(fl * __log2f(fabsf(lam)));
                if ((t & 1) && lam < 0.0f) v = -v;
            }
        } else if (ch < 6) {
            int h = ch - 3;
            float x  = nu[h];
            // sigmoid(x)^L = exp2(-L * log2(1 + e^-x))
            float lg  = -__log2f(1.0f + __expf(-x));
            float mag = exp2f(fl * lg);
            float ang = theta[h] * fl;
            v = mag * ((h == 2) ? __sinf(ang) : __cosf(ang));
        } else {
            int h = ch - 3;          // 3, 4
            float ang = theta[h] * fl;
            v = (h == 3) ? __cosf(ang) : __sinf(ang);
        }
        tab[t] = v;
    }
    __syncthreads();

    int farth;                    // groups with jb < i - farth are "far"
    if      (ch == 2) farth = 806;
    else if (ch == 6) farth = 608;
    else              farth = 203;

    #pragma unroll
    for (int r = 0; r < RPB; r++) {
        const int i = i0 + r;
        float4* __restrict__ row4 =
            (float4*)(out + ((size_t)ch * TRUNC + (size_t)i) * TLEN);

        // far-region pattern for this (ch, i): j-independent except ch6
        float4 farv;
        if (ch == 2) {
            int im = i & 3;
            farv.x = (im == 0) ? 1.f : 0.f;
            farv.y = (im == 1) ? 1.f : 0.f;
            farv.z = (im == 2) ? 1.f : 0.f;
            farv.w = (im == 3) ? 1.f : 0.f;
        } else if (ch == 5 || ch == 7) {
            farv = zero4;
        } else {
            farv = make_float4(1.f, 1.f, 1.f, 1.f);
        }

        #pragma unroll
        for (int g = 0; g < 2; g++) {
            int q  = t + (g << 8);
            int jb = q << 2;
            float4 rr;
            if (jb > i) {
                rr = zero4;
            } else if (jb < i - farth) {
                if (ch == 6) {
                    unsigned r3 = (unsigned)(i - jb) % 3u;
                    rr.x = (r3 == 0u) ? 1.f : 0.f;
                    rr.y = (r3 == 1u) ? 1.f : 0.f;
                    rr.z = (r3 == 2u) ? 1.f : 0.f;
                    rr.w = (r3 == 0u) ? 1.f : 0.f;
                } else {
                    rr = farv;
                }
            } else {
                // diagonal band: table lookups (general path, covers all d >= 0)
                #pragma unroll
                for (int k = 0; k < 4; k++) {
                    int d = i - jb - k;
                    float v = 0.0f;
                    if (d >= 0) {
                        if (ch == 2) {
                            if ((d & 3) == 0) {
                                int dq = d >> 2;
                                v = tab[(dq > CAPV) ? 0 : dq];
                            }
                        } else if (ch == 6) {
                            unsigned ud = (unsigned)d;
                            if (ud % 3u == 0u) {
                                unsigned dq = ud / 3u;
                                v = tab[(dq > CAPV) ? 0 : (int)dq]
                                  * tab[(d  > CAPV) ? 0 : d];
                            }
                        } else if (ch == 7) {
                            if (d <= CAPV && (d & 1) == 0)
                                v = tab[d >> 1] * tab[d];
                        } else {
                            v = tab[(d > CAPV) ? 0 : d];
                        }
                        if (d == 0) v -= 1.0f;
                    }
                    ((float*)&rr)[k] = v;
                }
            }
            row4[q] = rr;
        }
    }
}

extern "C" void kernel_launch(void* const* d_in, const int* in_sizes, int n_in,
                              void* d_out, int out_size)
{
    const float* eta   = (const float*)d_in[0];
    const float* nu    = (const float*)d_in[1];
    const float* theta = (const float*)d_in[2];
    float* out = (float*)d_out;

    rem_kernel<<<dim3(TRUNC / RPB, 8), 256>>>(eta, nu, theta, out);
}